// round 1
// baseline (speedup 1.0000x reference)
#include <cuda_runtime.h>
#include <math_constants.h>

// Shapes (fixed per reference setup_inputs)
#define N_SPATIAL 128           // n
#define DEPTH     2048          // channels
#define NPOS      (N_SPATIAL * N_SPATIAL)     // 16384 spatial positions
#define TOTAL     (NPOS * DEPTH)              // 33,554,432 elements

// Pass-1 tiling
#define NCHUNK    128                          // spatial chunks
#define PS        (NPOS / NCHUNK)              // 128 positions per chunk
#define P1_TPB    256                          // threads per block
#define CH_PER_T  4                            // channels per thread (float4)
#define CH_GROUPS (DEPTH / (P1_TPB * CH_PER_T))// 2

// Scratch (allocation-free: __device__ globals)
__device__ float g_pmax[NCHUNK * DEPTH];
__device__ int   g_pidx[NCHUNK * DEPTH];
__device__ int   g_argidx[DEPTH];

// ---------------------------------------------------------------------------
// Pass 1: per-(chunk, channel) partial argmax.
// Thread t in channel-group g handles 4 consecutive channels via float4 loads;
// warp reads 512B contiguous per spatial position -> fully coalesced.
// Ascending p with strict '>' preserves first-occurrence semantics in-chunk.
// ---------------------------------------------------------------------------
__global__ void __launch_bounds__(P1_TPB)
partial_argmax_kernel(const float* __restrict__ x)
{
    const int chunk = blockIdx.y;                      // 0..NCHUNK-1
    const int c4 = (blockIdx.x * P1_TPB + threadIdx.x) * CH_PER_T; // channel base
    const int p0 = chunk * PS;

    float m0 = -CUDART_INF_F, m1 = -CUDART_INF_F, m2 = -CUDART_INF_F, m3 = -CUDART_INF_F;
    int i0 = 0, i1 = 0, i2 = 0, i3 = 0;

    const float4* __restrict__ xp =
        reinterpret_cast<const float4*>(x + (size_t)p0 * DEPTH + c4);
    const int stride4 = DEPTH / 4;                     // float4 stride per position

    #pragma unroll 4
    for (int p = 0; p < PS; p++) {
        float4 v = __ldg(xp + (size_t)p * stride4);
        int pidx = p0 + p;
        if (v.x > m0) { m0 = v.x; i0 = pidx; }
        if (v.y > m1) { m1 = v.y; i1 = pidx; }
        if (v.z > m2) { m2 = v.z; i2 = pidx; }
        if (v.w > m3) { m3 = v.w; i3 = pidx; }
    }

    float* pm = &g_pmax[(size_t)chunk * DEPTH + c4];
    int*   pi = &g_pidx[(size_t)chunk * DEPTH + c4];
    pm[0] = m0; pm[1] = m1; pm[2] = m2; pm[3] = m3;
    pi[0] = i0; pi[1] = i1; pi[2] = i2; pi[3] = i3;
}

// ---------------------------------------------------------------------------
// Pass 2: fold NCHUNK partials per channel. Ascending chunk + strict '>'
// keeps the smallest spatial index among equal maxima (first occurrence).
// ---------------------------------------------------------------------------
__global__ void reduce_argmax_kernel()
{
    const int c = blockIdx.x * blockDim.x + threadIdx.x;   // channel
    if (c >= DEPTH) return;

    float best = g_pmax[c];
    int   bidx = g_pidx[c];
    #pragma unroll 8
    for (int k = 1; k < NCHUNK; k++) {
        float m = g_pmax[(size_t)k * DEPTH + c];
        int   i = g_pidx[(size_t)k * DEPTH + c];
        if (m > best) { best = m; bidx = i; }
    }
    g_argidx[c] = bidx;
}

// ---------------------------------------------------------------------------
// Pass 3: out = x * max(-1, 1 - l1/128), with the reference's transposed
// coordinates: i_max = idx % 128 compared to row i, j_max = idx / 128 to col j.
// ---------------------------------------------------------------------------
__global__ void __launch_bounds__(256)
apply_mask_kernel(const float* __restrict__ x, float* __restrict__ out)
{
    const int gid = blockIdx.x * blockDim.x + threadIdx.x;   // float4 index
    const int e  = gid << 2;                                  // element index
    const int d4 = e & (DEPTH - 1);                           // channel base
    const int s  = e >> 11;                                   // spatial index
    const int i  = s >> 7;                                    // row
    const int j  = s & 127;                                   // col

    int4  idx = __ldg(reinterpret_cast<const int4*>(&g_argidx[d4]));
    float4 v  = __ldg(reinterpret_cast<const float4*>(x) + gid);

    const float inv_n = 1.0f / (float)N_SPATIAL;

    int l1x = abs(i - (idx.x & 127)) + abs(j - (idx.x >> 7));
    int l1y = abs(i - (idx.y & 127)) + abs(j - (idx.y >> 7));
    int l1z = abs(i - (idx.z & 127)) + abs(j - (idx.z >> 7));
    int l1w = abs(i - (idx.w & 127)) + abs(j - (idx.w >> 7));

    float4 o;
    o.x = v.x * fmaxf(-1.0f, 1.0f - (float)l1x * inv_n);
    o.y = v.y * fmaxf(-1.0f, 1.0f - (float)l1y * inv_n);
    o.z = v.z * fmaxf(-1.0f, 1.0f - (float)l1z * inv_n);
    o.w = v.w * fmaxf(-1.0f, 1.0f - (float)l1w * inv_n);

    reinterpret_cast<float4*>(out)[gid] = o;
}

extern "C" void kernel_launch(void* const* d_in, const int* in_sizes, int n_in,
                              void* d_out, int out_size)
{
    const float* x = (const float*)d_in[0];
    float* out = (float*)d_out;

    dim3 g1(CH_GROUPS, NCHUNK);
    partial_argmax_kernel<<<g1, P1_TPB>>>(x);

    reduce_argmax_kernel<<<(DEPTH + 255) / 256, 256>>>();

    const int n4 = TOTAL / 4;
    apply_mask_kernel<<<n4 / 256, 256>>>(x, out);
}

// round 2
// speedup vs baseline: 1.0250x; 1.0250x over previous
#include <cuda_runtime.h>
#include <math_constants.h>

// Shapes (fixed per reference setup_inputs)
#define N_SPATIAL 128           // n
#define DEPTH     2048          // channels
#define NPOS      (N_SPATIAL * N_SPATIAL)     // 16384 spatial positions
#define TOTAL     (NPOS * DEPTH)              // 33,554,432 elements

// Pass-1 tiling: many small chunks -> high occupancy to hide DRAM latency
#define NCHUNK    512                          // spatial chunks
#define PS        (NPOS / NCHUNK)              // 32 positions per chunk
#define P1_TPB    256                          // threads per block
#define CH_PER_T  4                            // channels per thread (float4)
#define CH_GROUPS (DEPTH / (P1_TPB * CH_PER_T))// 2

// Pass-2 two-level reduce
#define RGROUPS   8                            // chunk groups
#define RCHUNKS   (NCHUNK / RGROUPS)           // 64 chunks per group

// Pass-3 ILP
#define P3_VEC    4                            // float4 per thread

// Scratch (allocation-free: __device__ globals)
__device__ float g_pmax[NCHUNK * DEPTH];
__device__ int   g_pidx[NCHUNK * DEPTH];
__device__ float g_p2max[RGROUPS * DEPTH];
__device__ int   g_p2idx[RGROUPS * DEPTH];
__device__ int   g_argidx[DEPTH];

// ---------------------------------------------------------------------------
// Pass 1: per-(chunk, channel) partial argmax.
// Chunks processed in REVERSE order (high spatial addresses first) so the
// low-address tail of x is the freshest content in L2 when pass 3 starts
// reading forward from address 0.
// Ascending p with strict '>' preserves first-occurrence semantics in-chunk.
// ---------------------------------------------------------------------------
__global__ void __launch_bounds__(P1_TPB)
partial_argmax_kernel(const float* __restrict__ x)
{
    const int chunk = (NCHUNK - 1) - blockIdx.y;       // reversed order
    const int c4 = (blockIdx.x * P1_TPB + threadIdx.x) * CH_PER_T; // channel base
    const int p0 = chunk * PS;

    float m0 = -CUDART_INF_F, m1 = -CUDART_INF_F, m2 = -CUDART_INF_F, m3 = -CUDART_INF_F;
    int i0 = 0, i1 = 0, i2 = 0, i3 = 0;

    const float4* __restrict__ xp =
        reinterpret_cast<const float4*>(x + (size_t)p0 * DEPTH + c4);
    const int stride4 = DEPTH / 4;                     // float4 stride per position

    #pragma unroll 8
    for (int p = 0; p < PS; p++) {
        float4 v = __ldg(xp + (size_t)p * stride4);
        int pidx = p0 + p;
        if (v.x > m0) { m0 = v.x; i0 = pidx; }
        if (v.y > m1) { m1 = v.y; i1 = pidx; }
        if (v.z > m2) { m2 = v.z; i2 = pidx; }
        if (v.w > m3) { m3 = v.w; i3 = pidx; }
    }

    float* pm = &g_pmax[(size_t)chunk * DEPTH + c4];
    int*   pi = &g_pidx[(size_t)chunk * DEPTH + c4];
    pm[0] = m0; pm[1] = m1; pm[2] = m2; pm[3] = m3;
    pi[0] = i0; pi[1] = i1; pi[2] = i2; pi[3] = i3;
}

// ---------------------------------------------------------------------------
// Pass 2a: fold RCHUNKS partials per (group, channel). Consecutive threads ->
// consecutive channels -> coalesced. Ascending chunk + strict '>' keeps the
// smallest spatial index among equal maxima (chunks are spatially ordered).
// ---------------------------------------------------------------------------
__global__ void __launch_bounds__(256)
reduce_argmax_stage1(void)
{
    const int t = blockIdx.x * blockDim.x + threadIdx.x;  // 0..RGROUPS*DEPTH-1
    const int c = t & (DEPTH - 1);
    const int q = t >> 11;                                // group

    const int k0 = q * RCHUNKS;
    float best = g_pmax[(size_t)k0 * DEPTH + c];
    int   bidx = g_pidx[(size_t)k0 * DEPTH + c];
    #pragma unroll 8
    for (int k = 1; k < RCHUNKS; k++) {
        float m = g_pmax[(size_t)(k0 + k) * DEPTH + c];
        int   i = g_pidx[(size_t)(k0 + k) * DEPTH + c];
        if (m > best) { best = m; bidx = i; }
    }
    g_p2max[(size_t)q * DEPTH + c] = best;
    g_p2idx[(size_t)q * DEPTH + c] = bidx;
}

// ---------------------------------------------------------------------------
// Pass 2b: fold RGROUPS partials per channel (ascending group, strict '>').
// ---------------------------------------------------------------------------
__global__ void __launch_bounds__(256)
reduce_argmax_stage2(void)
{
    const int c = blockIdx.x * blockDim.x + threadIdx.x;  // channel
    float best = g_p2max[c];
    int   bidx = g_p2idx[c];
    #pragma unroll
    for (int q = 1; q < RGROUPS; q++) {
        float m = g_p2max[(size_t)q * DEPTH + c];
        int   i = g_p2idx[(size_t)q * DEPTH + c];
        if (m > best) { best = m; bidx = i; }
    }
    g_argidx[c] = bidx;
}

// ---------------------------------------------------------------------------
// Pass 3: out = x * max(-1, 1 - l1/128), with the reference's transposed
// coordinates: i_max = idx % 128 compared to row i, j_max = idx / 128 to col j.
// Each thread handles P3_VEC consecutive float4s (16 channels, same spatial
// position -> one i/j pair). Reads x forward from address 0 to harvest the
// L2 residue left by pass 1's reversed traversal.
// ---------------------------------------------------------------------------
__global__ void __launch_bounds__(256)
apply_mask_kernel(const float* __restrict__ x, float* __restrict__ out)
{
    const int tid  = blockIdx.x * blockDim.x + threadIdx.x;
    const int gid0 = tid * P3_VEC;                        // first float4 index
    const int e    = gid0 << 2;                           // element index
    const int d0   = e & (DEPTH - 1);                     // channel base (16-aligned)
    const int s    = e >> 11;                             // spatial index
    const int i    = s >> 7;                              // row
    const int j    = s & 127;                             // col

    const float inv_n = 1.0f / (float)N_SPATIAL;
    const float4* __restrict__ xv = reinterpret_cast<const float4*>(x);
    float4* __restrict__ ov = reinterpret_cast<float4*>(out);

    float4 v[P3_VEC];
    int4   idx[P3_VEC];
    #pragma unroll
    for (int k = 0; k < P3_VEC; k++) {
        v[k]   = __ldg(xv + gid0 + k);
        idx[k] = __ldg(reinterpret_cast<const int4*>(&g_argidx[d0 + 4 * k]));
    }

    #pragma unroll
    for (int k = 0; k < P3_VEC; k++) {
        int l1x = abs(i - (idx[k].x & 127)) + abs(j - (idx[k].x >> 7));
        int l1y = abs(i - (idx[k].y & 127)) + abs(j - (idx[k].y >> 7));
        int l1z = abs(i - (idx[k].z & 127)) + abs(j - (idx[k].z >> 7));
        int l1w = abs(i - (idx[k].w & 127)) + abs(j - (idx[k].w >> 7));

        float4 o;
        o.x = v[k].x * fmaxf(-1.0f, 1.0f - (float)l1x * inv_n);
        o.y = v[k].y * fmaxf(-1.0f, 1.0f - (float)l1y * inv_n);
        o.z = v[k].z * fmaxf(-1.0f, 1.0f - (float)l1z * inv_n);
        o.w = v[k].w * fmaxf(-1.0f, 1.0f - (float)l1w * inv_n);
        ov[gid0 + k] = o;
    }
}

extern "C" void kernel_launch(void* const* d_in, const int* in_sizes, int n_in,
                              void* d_out, int out_size)
{
    const float* x = (const float*)d_in[0];
    float* out = (float*)d_out;

    dim3 g1(CH_GROUPS, NCHUNK);
    partial_argmax_kernel<<<g1, P1_TPB>>>(x);

    reduce_argmax_stage1<<<(RGROUPS * DEPTH) / 256, 256>>>();
    reduce_argmax_stage2<<<DEPTH / 256, 256>>>();

    const int n_threads = TOTAL / 4 / P3_VEC;             // float4s / vec
    apply_mask_kernel<<<n_threads / 256, 256>>>(x, out);
}

// round 3
// speedup vs baseline: 1.2714x; 1.2403x over previous
#include <cuda_runtime.h>
#include <math_constants.h>

// Shapes (fixed per reference setup_inputs)
#define N_SPATIAL 128           // n
#define DEPTH     2048          // channels
#define NPOS      (N_SPATIAL * N_SPATIAL)     // 16384 spatial positions
#define TOTAL     (NPOS * DEPTH)              // 33,554,432 elements

// Pass-1 tiling
#define NCHUNK    512                          // spatial chunks
#define PS        (NPOS / NCHUNK)              // 32 positions per chunk
#define P1_TPB    256
#define CH_PER_T  4                            // channels per thread (float4)
#define CH_GROUPS (DEPTH / (P1_TPB * CH_PER_T))// 2
#define BATCH     8                            // in-flight float4 loads per thread

// Pass-2 two-level reduce
#define RGROUPS   8
#define RCHUNKS   (NCHUNK / RGROUPS)           // 64

// Pass-3 tiling (chunk stays inside one spatial row -> i constant per CTA)
#define P3_PS     32
#define P3_NCHUNK (NPOS / P3_PS)               // 512

// Scratch (allocation-free: __device__ globals)
__device__ float g_pmax[NCHUNK * DEPTH];
__device__ int   g_pidx[NCHUNK * DEPTH];
__device__ float g_p2max[RGROUPS * DEPTH];
__device__ int   g_p2idx[RGROUPS * DEPTH];
__device__ int   g_argidx[DEPTH];

// ---------------------------------------------------------------------------
// Pass 1: per-(chunk, channel) partial argmax. Reverse chunk order so low
// addresses of x are freshest in L2 when pass 3 reads forward.
// Explicit BATCH-deep register buffer forces high MLP.
// ---------------------------------------------------------------------------
__global__ void __launch_bounds__(P1_TPB)
partial_argmax_kernel(const float* __restrict__ x)
{
    const int chunk = (NCHUNK - 1) - blockIdx.y;       // reversed order
    const int c4 = (blockIdx.x * P1_TPB + threadIdx.x) * CH_PER_T;
    const int p0 = chunk * PS;

    float m0 = -CUDART_INF_F, m1 = -CUDART_INF_F, m2 = -CUDART_INF_F, m3 = -CUDART_INF_F;
    int i0 = 0, i1 = 0, i2 = 0, i3 = 0;

    const float4* __restrict__ xp =
        reinterpret_cast<const float4*>(x + (size_t)p0 * DEPTH + c4);
    const int stride4 = DEPTH / 4;

    for (int pb = 0; pb < PS; pb += BATCH) {
        float4 buf[BATCH];
        #pragma unroll
        for (int u = 0; u < BATCH; u++)
            buf[u] = __ldg(xp + (size_t)(pb + u) * stride4);

        #pragma unroll
        for (int u = 0; u < BATCH; u++) {
            int pidx = p0 + pb + u;
            if (buf[u].x > m0) { m0 = buf[u].x; i0 = pidx; }
            if (buf[u].y > m1) { m1 = buf[u].y; i1 = pidx; }
            if (buf[u].z > m2) { m2 = buf[u].z; i2 = pidx; }
            if (buf[u].w > m3) { m3 = buf[u].w; i3 = pidx; }
        }
    }

    float* pm = &g_pmax[(size_t)chunk * DEPTH + c4];
    int*   pi = &g_pidx[(size_t)chunk * DEPTH + c4];
    pm[0] = m0; pm[1] = m1; pm[2] = m2; pm[3] = m3;
    pi[0] = i0; pi[1] = i1; pi[2] = i2; pi[3] = i3;
}

// ---------------------------------------------------------------------------
// Pass 2a/2b: fold partials. Ascending chunk order + strict '>' keeps the
// first-occurrence (smallest flat index) among equal maxima.
// ---------------------------------------------------------------------------
__global__ void __launch_bounds__(256)
reduce_argmax_stage1(void)
{
    const int t = blockIdx.x * blockDim.x + threadIdx.x;
    const int c = t & (DEPTH - 1);
    const int q = t >> 11;

    const int k0 = q * RCHUNKS;
    float best = g_pmax[(size_t)k0 * DEPTH + c];
    int   bidx = g_pidx[(size_t)k0 * DEPTH + c];
    #pragma unroll 8
    for (int k = 1; k < RCHUNKS; k++) {
        float m = g_pmax[(size_t)(k0 + k) * DEPTH + c];
        int   i = g_pidx[(size_t)(k0 + k) * DEPTH + c];
        if (m > best) { best = m; bidx = i; }
    }
    g_p2max[(size_t)q * DEPTH + c] = best;
    g_p2idx[(size_t)q * DEPTH + c] = bidx;
}

__global__ void __launch_bounds__(256)
reduce_argmax_stage2(void)
{
    const int c = blockIdx.x * blockDim.x + threadIdx.x;
    float best = g_p2max[c];
    int   bidx = g_p2idx[c];
    #pragma unroll
    for (int q = 1; q < RGROUPS; q++) {
        float m = g_p2max[(size_t)q * DEPTH + c];
        int   i = g_p2idx[(size_t)q * DEPTH + c];
        if (m > best) { best = m; bidx = i; }
    }
    g_argidx[c] = bidx;
}

// ---------------------------------------------------------------------------
// Pass 3: out = x * max(-1, 1 - l1/128) with the reference's transposed
// coords (i_max = idx % 128, j_max = idx / 128).
// Channel-resident: thread owns 4 channels, loads argidx ONCE, streams 32
// positions of one spatial row (i constant -> fb = 1 - |i-im|/128 is a
// per-thread constant; only |j-jm| varies). Streaming cache hints keep L2
// clean for the input residue.
// ---------------------------------------------------------------------------
__global__ void __launch_bounds__(P1_TPB)
apply_mask_kernel(const float* __restrict__ x, float* __restrict__ out)
{
    const int chunk = blockIdx.y;                       // 0..511
    const int c4 = (blockIdx.x * P1_TPB + threadIdx.x) * CH_PER_T;
    const int p0 = chunk * P3_PS;
    const int i  = p0 >> 7;                             // row (constant in chunk)
    const int j0 = p0 & 127;                            // starting col

    const float inv_n = 1.0f / (float)N_SPATIAL;

    int4 idx = __ldg(reinterpret_cast<const int4*>(&g_argidx[c4]));
    const int jm0 = idx.x >> 7, jm1 = idx.y >> 7, jm2 = idx.z >> 7, jm3 = idx.w >> 7;
    const float fb0 = 1.0f - (float)abs(i - (idx.x & 127)) * inv_n;
    const float fb1 = 1.0f - (float)abs(i - (idx.y & 127)) * inv_n;
    const float fb2 = 1.0f - (float)abs(i - (idx.z & 127)) * inv_n;
    const float fb3 = 1.0f - (float)abs(i - (idx.w & 127)) * inv_n;

    const float4* __restrict__ xp =
        reinterpret_cast<const float4*>(x + (size_t)p0 * DEPTH + c4);
    float4* __restrict__ op =
        reinterpret_cast<float4*>(out + (size_t)p0 * DEPTH + c4);
    const int stride4 = DEPTH / 4;

    for (int pb = 0; pb < P3_PS; pb += BATCH) {
        float4 buf[BATCH];
        #pragma unroll
        for (int u = 0; u < BATCH; u++)
            buf[u] = __ldcs(xp + (size_t)(pb + u) * stride4);

        #pragma unroll
        for (int u = 0; u < BATCH; u++) {
            const int j = j0 + pb + u;
            float k0 = fmaxf(-1.0f, fb0 - (float)abs(j - jm0) * inv_n);
            float k1 = fmaxf(-1.0f, fb1 - (float)abs(j - jm1) * inv_n);
            float k2 = fmaxf(-1.0f, fb2 - (float)abs(j - jm2) * inv_n);
            float k3 = fmaxf(-1.0f, fb3 - (float)abs(j - jm3) * inv_n);
            float4 o;
            o.x = buf[u].x * k0;
            o.y = buf[u].y * k1;
            o.z = buf[u].z * k2;
            o.w = buf[u].w * k3;
            __stcs(op + (size_t)(pb + u) * stride4, o);
        }
    }
}

extern "C" void kernel_launch(void* const* d_in, const int* in_sizes, int n_in,
                              void* d_out, int out_size)
{
    const float* x = (const float*)d_in[0];
    float* out = (float*)d_out;

    dim3 g1(CH_GROUPS, NCHUNK);
    partial_argmax_kernel<<<g1, P1_TPB>>>(x);

    reduce_argmax_stage1<<<(RGROUPS * DEPTH) / 256, 256>>>();
    reduce_argmax_stage2<<<DEPTH / 256, 256>>>();

    dim3 g3(CH_GROUPS, P3_NCHUNK);
    apply_mask_kernel<<<g3, P1_TPB>>>(x, out);
}